// round 14
// baseline (speedup 1.0000x reference)
#include <cuda_runtime.h>
#include <cuda_fp16.h>
#include <cstdint>
#include <cstddef>

#define KCODES 8192
#define DDIM   256
#define NROWS  32768
#define GAMMA_F 0.99f
#define EPS_F   1e-5f

#define NKC  8              // K-chunks of 32 halves (K=256)
#define NS   4              // cp.async pipeline stages
#define LDH  40             // padded halves per smem row (80B)
#define GEMM_SMEM (2 * NS * 128 * LDH * 2)   // 81920 B
#define MARGIN 0.15f
#define NGRP (KCODES / 16)  // 512 16-code groups
#define NTIL (KCODES / 64)  // 128 64-code tiles
#define NROWT (NROWS / 128) // 256 row tiles
#define NCOLT (KCODES / 128)// 64 col tiles

// ---------------- device scratch ----------------
__device__ __half g_Az[(size_t)NROWS * DDIM];
__device__ __half g_Bw[(size_t)KCODES * DDIM];
__device__ float g_S[(size_t)NROWS * NGRP];      // per (row,16-code group) max approx score
__device__ float g_T[(size_t)NROWS * NTIL];      // per (row,64-code tile)  max approx score
__device__ unsigned g_rmax[NROWS];               // per-row max approx score (ordered uint)
__device__ unsigned g_done[NROWT];               // per-rowtile completion counters
__device__ float g_wnorm[KCODES];
__device__ float g_cnt[KCODES];
__device__ float g_commit;
__device__ float g_nsum;

// ---------------- helpers ----------------
__device__ __forceinline__ uint32_t smem_u32(const void* p) {
    uint32_t a;
    asm("{ .reg .u64 t; cvta.to.shared.u64 t, %1; cvt.u32.u64 %0, t; }" : "=r"(a) : "l"(p));
    return a;
}
__device__ __forceinline__ void cp16(uint32_t s, const void* g) {
    asm volatile("cp.async.cg.shared.global [%0], [%1], 16;" :: "r"(s), "l"(g));
}
#define CP_COMMIT() asm volatile("cp.async.commit_group;" ::: "memory")
#define CP_WAIT(n)  asm volatile("cp.async.wait_group %0;" :: "n"(n) : "memory")

__device__ __forceinline__ void ldsm4(uint32_t* r, uint32_t addr) {
    asm volatile("ldmatrix.sync.aligned.m8n8.x4.shared.b16 {%0,%1,%2,%3}, [%4];"
                 : "=r"(r[0]), "=r"(r[1]), "=r"(r[2]), "=r"(r[3]) : "r"(addr));
}
__device__ __forceinline__ void mma16816(float* c, const uint32_t* a,
                                         uint32_t b0, uint32_t b1) {
    asm volatile(
        "mma.sync.aligned.m16n8k16.row.col.f32.f16.f16.f32 "
        "{%0,%1,%2,%3}, {%4,%5,%6,%7}, {%8,%9}, {%0,%1,%2,%3};"
        : "+f"(c[0]), "+f"(c[1]), "+f"(c[2]), "+f"(c[3])
        : "r"(a[0]), "r"(a[1]), "r"(a[2]), "r"(a[3]), "r"(b0), "r"(b1));
}
__device__ __forceinline__ unsigned ordf(float s) {
    unsigned u = __float_as_uint(s);
    return (u & 0x80000000u) ? ~u : (u | 0x80000000u);
}
__device__ __forceinline__ float unordf(unsigned u) {
    u = (u & 0x80000000u) ? (u & 0x7fffffffu) : ~u;
    return __uint_as_float(u);
}
__device__ __forceinline__ unsigned long long fkey(float s, int code) {
    return ((unsigned long long)ordf(s) << 32) | (unsigned)(KCODES - 1 - code);
}
__device__ __forceinline__ unsigned long long umax64(unsigned long long a, unsigned long long b) {
    return a > b ? a : b;
}

// ---------------- prep: casts + mt seed + wnorm + counter zeroing ----------------
__global__ void k_prep(const float* __restrict__ ze, const float* __restrict__ W,
                       const float* __restrict__ mt, float* __restrict__ out_mt) {
    int i = blockIdx.x * 256 + threadIdx.x;       // covers NROWS*DDIM
    g_Az[i] = __float2half_rn(ze[i]);
    if (i < KCODES * DDIM) {
        g_Bw[i] = __float2half_rn(W[i]);
        out_mt[i] = GAMMA_F * mt[i];
    }
    if (i < NROWS) g_rmax[i] = 0u;
    if (i < KCODES) {
        const float4* w = (const float4*)(W + (size_t)i * DDIM);
        float s = 0.f;
        #pragma unroll 8
        for (int q = 0; q < DDIM / 4; ++q) {
            float4 v = w[q];
            s += v.x * v.x + v.y * v.y + v.z * v.z + v.w * v.w;
        }
        g_wnorm[i] = 0.5f * s;
        g_cnt[i]   = 0.f;
    }
    if (i < NROWT) g_done[i] = 0u;
    if (i == 0) { g_commit = 0.f; g_nsum = 0.f; }
}

// ---------------- fused: fp16 HMMA GEMM + per-rowtile phase2 (last CTA) ----------------
__global__ void __launch_bounds__(256, 2) k_gemm1(
        const float* __restrict__ ze, const float* __restrict__ W,
        float* __restrict__ out_zq, float* __restrict__ out_idx,
        float* __restrict__ out_mt) {
    extern __shared__ __half dsm[];
    __half* sAb = dsm;                       // [NS][128*LDH]
    __half* sBb = dsm + NS * 128 * LDH;

    const int tid  = threadIdx.x;
    const int wid  = tid >> 5;
    const int lane = tid & 31;
    const int nBase    = blockIdx.x * 128;   // coltile fast -> rowtiles finish early
    const int rowTile  = blockIdx.y;
    const int rowBase  = rowTile * 128;

    const int lr = tid >> 2;
    const int lc = tid & 3;
    uint32_t aS[NS], bS[NS];
    #pragma unroll
    for (int s = 0; s < NS; ++s) {
        aS[s] = smem_u32(sAb + s * 128 * LDH);
        bS[s] = smem_u32(sBb + s * 128 * LDH);
    }

    {
        float acc[2][8][4];
        #pragma unroll
        for (int i = 0; i < 2; ++i)
            #pragma unroll
            for (int j = 0; j < 8; ++j)
                #pragma unroll
                for (int q = 0; q < 4; ++q) acc[i][j][q] = 0.f;

        // prologue: stages 0..NS-2
        #pragma unroll
        for (int s = 0; s < NS - 1; ++s) {
            const int ko = s * 32;
            #pragma unroll
            for (int p = 0; p < 2; ++p) {
                int r = lr + 64 * p;
                cp16(aS[s] + r * (LDH * 2) + lc * 16,
                     g_Az + (size_t)(rowBase + r) * DDIM + ko + lc * 8);
                cp16(bS[s] + r * (LDH * 2) + lc * 16,
                     g_Bw + (size_t)(nBase + r) * DDIM + ko + lc * 8);
            }
            CP_COMMIT();
        }

        const int mOff = (wid >> 1) * 32;
        const int nOff = (wid & 1) * 64;
        const int lmRow = lane & 15;
        const int lmCol = (lane >> 4) * 16;

        for (int kc = 0; kc < NKC; ++kc) {
            CP_WAIT(NS - 2);
            __syncthreads();
            {
                const int nc = kc + NS - 1;
                if (nc < NKC) {
                    const int st = nc & (NS - 1);
                    const int ko = nc * 32;
                    #pragma unroll
                    for (int p = 0; p < 2; ++p) {
                        int r = lr + 64 * p;
                        cp16(aS[st] + r * (LDH * 2) + lc * 16,
                             g_Az + (size_t)(rowBase + r) * DDIM + ko + lc * 8);
                        cp16(bS[st] + r * (LDH * 2) + lc * 16,
                             g_Bw + (size_t)(nBase + r) * DDIM + ko + lc * 8);
                    }
                }
                CP_COMMIT();
            }

            const int buf = kc & (NS - 1);
            #pragma unroll
            for (int k16 = 0; k16 < 2; ++k16) {
                const int kb = k16 * 32 + lmCol;
                uint32_t af[2][4];
                #pragma unroll
                for (int i = 0; i < 2; ++i)
                    ldsm4(af[i], aS[buf] + (mOff + i * 16 + lmRow) * (LDH * 2) + kb);
                uint32_t bf[4][4];
                #pragma unroll
                for (int g = 0; g < 4; ++g)
                    ldsm4(bf[g], bS[buf] + (nOff + g * 16 + lmRow) * (LDH * 2) + kb);
                #pragma unroll
                for (int i = 0; i < 2; ++i)
                    #pragma unroll
                    for (int j = 0; j < 8; ++j) {
                        const int g = j >> 1, h = j & 1;
                        mma16816(acc[i][j], af[i], bf[g][h], bf[g][h + 2]);
                    }
            }
        }

        // epilogue: per-group / per-tile maxima + per-row running max
        const int gBase = (nBase + nOff) >> 4;
        const int tIdx  = (nBase + nOff) >> 6;
        #pragma unroll
        for (int i = 0; i < 2; ++i) {
            const int r0 = rowBase + mOff + i * 16 + (lane >> 2);   // rows r0, r0+8
            float ta = -3.4e38f, tb = -3.4e38f;
            #pragma unroll
            for (int t = 0; t < 4; ++t) {
                float sa = -3.4e38f, sb = -3.4e38f;
                #pragma unroll
                for (int jj = 0; jj < 2; ++jj) {
                    const int j = 2 * t + jj;
                    const int col = nBase + nOff + j * 8 + (lane & 3) * 2;
                    const float wn0 = __ldg(&g_wnorm[col]);
                    const float wn1 = __ldg(&g_wnorm[col + 1]);
                    sa = fmaxf(sa, fmaxf(acc[i][j][0] - wn0, acc[i][j][1] - wn1));
                    sb = fmaxf(sb, fmaxf(acc[i][j][2] - wn0, acc[i][j][3] - wn1));
                }
                sa = fmaxf(sa, __shfl_xor_sync(0xffffffffu, sa, 1));
                sa = fmaxf(sa, __shfl_xor_sync(0xffffffffu, sa, 2));
                sb = fmaxf(sb, __shfl_xor_sync(0xffffffffu, sb, 1));
                sb = fmaxf(sb, __shfl_xor_sync(0xffffffffu, sb, 2));
                ta = fmaxf(ta, sa);
                tb = fmaxf(tb, sb);
                if ((lane & 3) == 0) {
                    g_S[(size_t)r0 * NGRP + gBase + t]       = sa;
                    g_S[(size_t)(r0 + 8) * NGRP + gBase + t] = sb;
                }
            }
            if ((lane & 3) == 0) {
                g_T[(size_t)r0 * NTIL + tIdx]       = ta;
                g_T[(size_t)(r0 + 8) * NTIL + tIdx] = tb;
                atomicMax(&g_rmax[r0],     ordf(ta));
                atomicMax(&g_rmax[r0 + 8], ordf(tb));
            }
        }
    }

    // ---- rowtile completion counter ----
    __threadfence();
    __syncthreads();
    __shared__ unsigned s_done;
    if (tid == 0) s_done = atomicAdd(&g_done[rowTile], 1u);
    __syncthreads();
    if (s_done != NCOLT - 1) return;
    __threadfence();

    // ---- phase 2 (last CTA of this rowtile): 16 rows per warp ----
    float* zs = (float*)dsm + wid * DDIM;    // per-warp 1KB z-row buffer
    for (int rr = 0; rr < 16; ++rr) {
        const int row = rowBase + wid * 16 + rr;

        float4 z0, z1;
        {
            const float4* zg = (const float4*)(ze + (size_t)row * DDIM);
            z0 = zg[lane]; z1 = zg[lane + 32];
            ((float4*)zs)[lane]      = z0;
            ((float4*)zs)[lane + 32] = z1;
        }
        __syncwarp();

        const float thr = unordf(g_rmax[row]) - MARGIN;
        const float* Trow = g_T + (size_t)row * NTIL;
        const float* Srow = g_S + (size_t)row * NGRP;

        unsigned long long best = 0ull;
        const float* zh = zs + (lane & 1) * 128;
        #pragma unroll
        for (int i = 0; i < 4; ++i) {
            float tv = Trow[i * 32 + lane];
            unsigned tmask = __ballot_sync(0xffffffffu, tv >= thr);
            while (tmask) {
                const int tb = __ffs(tmask) - 1;
                tmask &= tmask - 1;
                const int tile = i * 32 + tb;
                float gsv = (lane < 4) ? Srow[tile * 4 + lane] : -3.4e38f;
                unsigned gmask = __ballot_sync(0xffffffffu, gsv >= thr) & 0xFu;
                while (gmask) {
                    const int gb = __ffs(gmask) - 1;
                    gmask &= gmask - 1;
                    const int g = tile * 4 + gb;
                    const int code = g * 16 + (lane >> 1);
                    const float* wp = W + (size_t)code * DDIM + (lane & 1) * 128;
                    float a0 = 0.f, a1 = 0.f, a2 = 0.f, a3 = 0.f;
                    #pragma unroll 8
                    for (int d = 0; d < 128; d += 16) {
                        float4 za = *(const float4*)(zh + d);
                        float4 zb = *(const float4*)(zh + d + 4);
                        float4 zc = *(const float4*)(zh + d + 8);
                        float4 zd = *(const float4*)(zh + d + 12);
                        float4 wa = *(const float4*)(wp + d);
                        float4 wb = *(const float4*)(wp + d + 4);
                        float4 wc = *(const float4*)(wp + d + 8);
                        float4 wd = *(const float4*)(wp + d + 12);
                        a0 = fmaf(za.x, wa.x, fmaf(za.y, wa.y, fmaf(za.z, wa.z, fmaf(za.w, wa.w, a0))));
                        a1 = fmaf(zb.x, wb.x, fmaf(zb.y, wb.y, fmaf(zb.z, wb.z, fmaf(zb.w, wb.w, a1))));
                        a2 = fmaf(zc.x, wc.x, fmaf(zc.y, wc.y, fmaf(zc.z, wc.z, fmaf(zc.w, wc.w, a2))));
                        a3 = fmaf(zd.x, wd.x, fmaf(zd.y, wd.y, fmaf(zd.z, wd.z, fmaf(zd.w, wd.w, a3))));
                    }
                    float accv = (a0 + a1) + (a2 + a3);
                    accv += __shfl_xor_sync(0xffffffffu, accv, 1);
                    if (!(lane & 1))
                        best = umax64(best, fkey(accv - __ldg(&g_wnorm[code]), code));
                }
            }
        }
        #pragma unroll
        for (int off = 16; off > 0; off >>= 1)
            best = umax64(best, __shfl_xor_sync(0xffffffffu, best, off));
        const int idx = KCODES - 1 - (int)(best & 0xffffffffu);

        // ---- fused scatter ----
        const float4* wg = (const float4*)(W + (size_t)idx * DDIM);
        float4 w0 = wg[lane], w1 = wg[lane + 32];

        float4* oq = (float4*)(out_zq + (size_t)row * DDIM);
        float4 q0, q1;   // straight-through: ze + (zq - ze)
        q0.x = z0.x + (w0.x - z0.x); q0.y = z0.y + (w0.y - z0.y);
        q0.z = z0.z + (w0.z - z0.z); q0.w = z0.w + (w0.w - z0.w);
        q1.x = z1.x + (w1.x - z1.x); q1.y = z1.y + (w1.y - z1.y);
        q1.z = z1.z + (w1.z - z1.z); q1.w = z1.w + (w1.w - z1.w);
        oq[lane] = q0; oq[lane + 32] = q1;

        float cs = 0.f;
        {
            float d;
            d = w0.x - z0.x; cs = fmaf(d, d, cs);
            d = w0.y - z0.y; cs = fmaf(d, d, cs);
            d = w0.z - z0.z; cs = fmaf(d, d, cs);
            d = w0.w - z0.w; cs = fmaf(d, d, cs);
            d = w1.x - z1.x; cs = fmaf(d, d, cs);
            d = w1.y - z1.y; cs = fmaf(d, d, cs);
            d = w1.z - z1.z; cs = fmaf(d, d, cs);
            d = w1.w - z1.w; cs = fmaf(d, d, cs);
        }
        #pragma unroll
        for (int off = 16; off > 0; off >>= 1)
            cs += __shfl_xor_sync(0xffffffffu, cs, off);

        const float s = 1.0f - GAMMA_F;
        float* mp = out_mt + (size_t)idx * DDIM + lane * 4;
        atomicAdd(mp + 0, s * z0.x); atomicAdd(mp + 1, s * z0.y);
        atomicAdd(mp + 2, s * z0.z); atomicAdd(mp + 3, s * z0.w);
        float* mp1 = mp + 128;
        atomicAdd(mp1 + 0, s * z1.x); atomicAdd(mp1 + 1, s * z1.y);
        atomicAdd(mp1 + 2, s * z1.z); atomicAdd(mp1 + 3, s * z1.w);

        if (lane == 0) {
            out_idx[row] = (float)idx;
            atomicAdd(&g_cnt[idx], 1.0f);
            atomicAdd(&g_commit, cs);
        }
    }
}

// ---------------- Nt_new + n ----------------
__global__ void k_fin_nt(const float* __restrict__ Nt, float* __restrict__ out_Nt) {
    int k = blockIdx.x * 256 + threadIdx.x;
    float v = GAMMA_F * Nt[k] + (1.0f - GAMMA_F) * g_cnt[k];
    out_Nt[k] = v;
    __shared__ float red[8];
    float s = v;
    #pragma unroll
    for (int off = 16; off > 0; off >>= 1)
        s += __shfl_down_sync(0xffffffffu, s, off);
    if ((threadIdx.x & 31) == 0) red[threadIdx.x >> 5] = s;
    __syncthreads();
    if (threadIdx.x < 8) {
        float t = red[threadIdx.x];
        #pragma unroll
        for (int off = 4; off > 0; off >>= 1)
            t += __shfl_down_sync(0xffu, t, off);
        if (threadIdx.x == 0) atomicAdd(&g_nsum, t);
    }
}

// ---------------- embedW_new + commit ----------------
__global__ void k_fin_w(const float* __restrict__ out_Nt,
                        const float* __restrict__ out_mt,
                        float* __restrict__ out_W,
                        float* __restrict__ out_commit) {
    int i = blockIdx.x * 256 + threadIdx.x;
    int k = i >> 8;
    float n  = g_nsum;
    float Nn = (out_Nt[k] + EPS_F) * n / (n + (float)KCODES * EPS_F);
    out_W[i] = out_mt[i] / Nn;
    if (i == 0) *out_commit = g_commit / (float)((size_t)NROWS * DDIM);
}

// ---------------- launch ----------------
extern "C" void kernel_launch(void* const* d_in, const int* in_sizes, int n_in,
                              void* d_out, int out_size) {
    const float* ze = (const float*)d_in[0];
    const float* W  = (const float*)d_in[1];
    const float* mt = (const float*)d_in[2];
    const float* Nt = (const float*)d_in[3];
    float* out = (float*)d_out;

    const size_t off_zq     = 0;
    const size_t off_commit = (size_t)NROWS * DDIM;
    const size_t off_idx    = off_commit + 1;
    const size_t off_W      = off_idx + NROWS;
    const size_t off_mt     = off_W + (size_t)KCODES * DDIM;
    const size_t off_Nt     = off_mt + (size_t)KCODES * DDIM;

    static int done = 0;
    if (!done) {
        cudaFuncSetAttribute(k_gemm1, cudaFuncAttributeMaxDynamicSharedMemorySize,
                             GEMM_SMEM);
        done = 1;
    }

    k_prep<<<(NROWS * DDIM) / 256, 256>>>(ze, W, mt, out + off_mt);

    dim3 grid(NCOLT, NROWT);   // x = coltile (fast) -> rowtiles complete early
    k_gemm1<<<grid, 256, GEMM_SMEM>>>(ze, W, out + off_zq, out + off_idx,
                                      out + off_mt);

    k_fin_nt<<<KCODES / 256, 256>>>(Nt, out + off_Nt);
    k_fin_w<<<(KCODES * DDIM) / 256, 256>>>(out + off_Nt, out + off_mt,
                                            out + off_W, out + off_commit);
}

// round 15
// speedup vs baseline: 1.1503x; 1.1503x over previous
#include <cuda_runtime.h>
#include <cuda_fp16.h>
#include <cstdint>
#include <cstddef>

#define KCODES 8192
#define DDIM   256
#define NROWS  32768
#define GAMMA_F 0.99f
#define EPS_F   1e-5f

#define NKC  8              // K-chunks of 32 halves (K=256)
#define NS   4              // cp.async pipeline stages
#define LDH  40             // padded halves per smem row (80B)
#define GEMM_SMEM (2 * NS * 128 * LDH * 2)   // 81920 B
#define MARGIN 0.15f
#define NGRP (KCODES / 8)   // 1024 8-code groups
#define NTIL (KCODES / 64)  // 128 64-code tiles

// ---------------- device scratch ----------------
__device__ __half g_Az[(size_t)NROWS * DDIM];
__device__ __half g_Bw[(size_t)KCODES * DDIM];
__device__ float g_S[(size_t)NROWS * NGRP];      // per (row,8-code group) max approx score
__device__ float g_T[(size_t)NROWS * NTIL];      // per (row,64-code tile) max approx score
__device__ float g_wnorm[KCODES];
__device__ float g_cnt[KCODES];
__device__ float g_commit;
__device__ float g_nsum;

// ---------------- helpers ----------------
__device__ __forceinline__ uint32_t smem_u32(const void* p) {
    uint32_t a;
    asm("{ .reg .u64 t; cvta.to.shared.u64 t, %1; cvt.u32.u64 %0, t; }" : "=r"(a) : "l"(p));
    return a;
}
__device__ __forceinline__ void cp16(uint32_t s, const void* g) {
    asm volatile("cp.async.cg.shared.global [%0], [%1], 16;" :: "r"(s), "l"(g));
}
#define CP_COMMIT() asm volatile("cp.async.commit_group;" ::: "memory")
#define CP_WAIT(n)  asm volatile("cp.async.wait_group %0;" :: "n"(n) : "memory")

__device__ __forceinline__ void ldsm4(uint32_t* r, uint32_t addr) {
    asm volatile("ldmatrix.sync.aligned.m8n8.x4.shared.b16 {%0,%1,%2,%3}, [%4];"
                 : "=r"(r[0]), "=r"(r[1]), "=r"(r[2]), "=r"(r[3]) : "r"(addr));
}
__device__ __forceinline__ void mma16816(float* c, const uint32_t* a,
                                         uint32_t b0, uint32_t b1) {
    asm volatile(
        "mma.sync.aligned.m16n8k16.row.col.f32.f16.f16.f32 "
        "{%0,%1,%2,%3}, {%4,%5,%6,%7}, {%8,%9}, {%0,%1,%2,%3};"
        : "+f"(c[0]), "+f"(c[1]), "+f"(c[2]), "+f"(c[3])
        : "r"(a[0]), "r"(a[1]), "r"(a[2]), "r"(a[3]), "r"(b0), "r"(b1));
}
__device__ __forceinline__ unsigned long long fkey(float s, int code) {
    unsigned u = __float_as_uint(s);
    u = (u & 0x80000000u) ? ~u : (u | 0x80000000u);
    return ((unsigned long long)u << 32) | (unsigned)(KCODES - 1 - code);
}
__device__ __forceinline__ unsigned long long umax64(unsigned long long a, unsigned long long b) {
    return a > b ? a : b;
}

// ---------------- prep: fp16 casts ----------------
__global__ void k_prep(const float* __restrict__ ze, const float* __restrict__ W) {
    int i = blockIdx.x * 256 + threadIdx.x;       // covers NROWS*DDIM
    g_Az[i] = __float2half_rn(ze[i]);
    if (i < KCODES * DDIM) g_Bw[i] = __float2half_rn(W[i]);
}

// ---------------- init: mt seed, wnorm, cnt, scalars ----------------
__global__ void k_init(const float* __restrict__ W, const float* __restrict__ mt,
                       float* __restrict__ out_mt) {
    int i = blockIdx.x * blockDim.x + threadIdx.x;
    out_mt[i] = GAMMA_F * mt[i];
    if (i < KCODES) {
        const float4* w = (const float4*)(W + (size_t)i * DDIM);
        float s = 0.f;
        #pragma unroll 8
        for (int q = 0; q < DDIM / 4; ++q) {
            float4 v = w[q];
            s += v.x * v.x + v.y * v.y + v.z * v.z + v.w * v.w;
        }
        g_wnorm[i] = 0.5f * s;
        g_cnt[i]   = 0.f;
    }
    if (i == 0) { g_commit = 0.f; g_nsum = 0.f; }
}

// ---------------- phase 1: fp16 HMMA (f32 accum) approx GEMM ----------------
__global__ void __launch_bounds__(256, 2) k_gemm1() {
    extern __shared__ __half dsm[];
    __half* sAb = dsm;                       // [NS][128*LDH]
    __half* sBb = dsm + NS * 128 * LDH;

    const int tid  = threadIdx.x;
    const int wid  = tid >> 5;
    const int lane = tid & 31;
    const int rowBase = blockIdx.x * 128;
    const int nBase   = blockIdx.y * 128;

    const int lr = tid >> 2;
    const int lc = tid & 3;
    uint32_t aS[NS], bS[NS];
    #pragma unroll
    for (int s = 0; s < NS; ++s) {
        aS[s] = smem_u32(sAb + s * 128 * LDH);
        bS[s] = smem_u32(sBb + s * 128 * LDH);
    }

    float acc[2][8][4];
    #pragma unroll
    for (int i = 0; i < 2; ++i)
        #pragma unroll
        for (int j = 0; j < 8; ++j)
            #pragma unroll
            for (int q = 0; q < 4; ++q) acc[i][j][q] = 0.f;

    // prologue: stages 0..NS-2
    #pragma unroll
    for (int s = 0; s < NS - 1; ++s) {
        const int ko = s * 32;
        #pragma unroll
        for (int p = 0; p < 2; ++p) {
            int r = lr + 64 * p;
            cp16(aS[s] + r * (LDH * 2) + lc * 16,
                 g_Az + (size_t)(rowBase + r) * DDIM + ko + lc * 8);
            cp16(bS[s] + r * (LDH * 2) + lc * 16,
                 g_Bw + (size_t)(nBase + r) * DDIM + ko + lc * 8);
        }
        CP_COMMIT();
    }

    const int mOff = (wid >> 1) * 32;
    const int nOff = (wid & 1) * 64;
    const int lmRow = lane & 15;
    const int lmCol = (lane >> 4) * 16;

    for (int kc = 0; kc < NKC; ++kc) {
        CP_WAIT(NS - 2);
        __syncthreads();
        {
            const int nc = kc + NS - 1;
            if (nc < NKC) {
                const int st = nc & (NS - 1);
                const int ko = nc * 32;
                #pragma unroll
                for (int p = 0; p < 2; ++p) {
                    int r = lr + 64 * p;
                    cp16(aS[st] + r * (LDH * 2) + lc * 16,
                         g_Az + (size_t)(rowBase + r) * DDIM + ko + lc * 8);
                    cp16(bS[st] + r * (LDH * 2) + lc * 16,
                         g_Bw + (size_t)(nBase + r) * DDIM + ko + lc * 8);
                }
            }
            CP_COMMIT();
        }

        const int buf = kc & (NS - 1);
        #pragma unroll
        for (int k16 = 0; k16 < 2; ++k16) {
            const int kb = k16 * 32 + lmCol;
            uint32_t af[2][4];
            #pragma unroll
            for (int i = 0; i < 2; ++i)
                ldsm4(af[i], aS[buf] + (mOff + i * 16 + lmRow) * (LDH * 2) + kb);
            uint32_t bf[4][4];
            #pragma unroll
            for (int g = 0; g < 4; ++g)
                ldsm4(bf[g], bS[buf] + (nOff + g * 16 + lmRow) * (LDH * 2) + kb);
            #pragma unroll
            for (int i = 0; i < 2; ++i)
                #pragma unroll
                for (int j = 0; j < 8; ++j) {
                    const int g = j >> 1, h = j & 1;
                    mma16816(acc[i][j], af[i], bf[g][h], bf[g][h + 2]);
                }
        }
    }

    // epilogue: per-8-code-group and per-64-code-tile max scores (unique writer)
    const int gBase = (nBase + nOff) >> 3;   // 8-code groups
    const int tIdx  = (nBase + nOff) >> 6;
    #pragma unroll
    for (int i = 0; i < 2; ++i) {
        const int r0 = rowBase + mOff + i * 16 + (lane >> 2);   // rows r0, r0+8
        float ta = -3.4e38f, tb = -3.4e38f;
        #pragma unroll
        for (int j = 0; j < 8; ++j) {
            const int col = nBase + nOff + j * 8 + (lane & 3) * 2;
            const float wn0 = __ldg(&g_wnorm[col]);
            const float wn1 = __ldg(&g_wnorm[col + 1]);
            float sa = fmaxf(acc[i][j][0] - wn0, acc[i][j][1] - wn1);
            float sb = fmaxf(acc[i][j][2] - wn0, acc[i][j][3] - wn1);
            sa = fmaxf(sa, __shfl_xor_sync(0xffffffffu, sa, 1));
            sa = fmaxf(sa, __shfl_xor_sync(0xffffffffu, sa, 2));
            sb = fmaxf(sb, __shfl_xor_sync(0xffffffffu, sb, 1));
            sb = fmaxf(sb, __shfl_xor_sync(0xffffffffu, sb, 2));
            ta = fmaxf(ta, sa);
            tb = fmaxf(tb, sb);
            if ((lane & 3) == 0) {
                g_S[(size_t)r0 * NGRP + gBase + j]       = sa;
                g_S[(size_t)(r0 + 8) * NGRP + gBase + j] = sb;
            }
        }
        if ((lane & 3) == 0) {
            g_T[(size_t)r0 * NTIL + tIdx]       = ta;
            g_T[(size_t)(r0 + 8) * NTIL + tIdx] = tb;
        }
    }
}

// ---------------- phase 2: hierarchical prune + exact fp32 rescore + fused scatter ----------------
__global__ void __launch_bounds__(256, 4) k_phase2(const float* __restrict__ ze,
                                                   const float* __restrict__ W,
                                                   float* __restrict__ out_zq,
                                                   float* __restrict__ out_idx,
                                                   float* __restrict__ out_mt) {
    __shared__ float zs[8][DDIM];
    const int wid  = threadIdx.x >> 5;
    const int lane = threadIdx.x & 31;
    const int row  = blockIdx.x * 8 + wid;

    float4 z0, z1;
    {
        const float4* zg = (const float4*)(ze + (size_t)row * DDIM);
        z0 = zg[lane]; z1 = zg[lane + 32];
        ((float4*)zs[wid])[lane]      = z0;
        ((float4*)zs[wid])[lane + 32] = z1;
    }
    __syncwarp();

    // scan per-tile maxima (128 floats)
    const float* Trow = g_T + (size_t)row * NTIL;
    float tv[4];
    float m = -3.4e38f;
    #pragma unroll
    for (int i = 0; i < 4; ++i) {
        tv[i] = Trow[i * 32 + lane];
        m = fmaxf(m, tv[i]);
    }
    #pragma unroll
    for (int off = 16; off > 0; off >>= 1)
        m = fmaxf(m, __shfl_xor_sync(0xffffffffu, m, off));
    const float thr = m - MARGIN;

    const float* Srow = g_S + (size_t)row * NGRP;
    unsigned long long best = 0ull;
    const float* zh = zs[wid] + (lane & 3) * 64;
    #pragma unroll
    for (int i = 0; i < 4; ++i) {
        unsigned tmask = __ballot_sync(0xffffffffu, tv[i] >= thr);
        while (tmask) {
            const int tb = __ffs(tmask) - 1;
            tmask &= tmask - 1;
            const int tile = i * 32 + tb;
            // this tile's 8 group scores (lanes 0-7)
            float gsv = (lane < 8) ? Srow[tile * 8 + lane] : -3.4e38f;
            unsigned gmask = __ballot_sync(0xffffffffu, gsv >= thr) & 0xFFu;
            while (gmask) {
                const int gb = __ffs(gmask) - 1;
                gmask &= gmask - 1;
                const int g = tile * 8 + gb;
                const int code = g * 8 + (lane >> 2);    // 4 lanes per code
                const float* wp = W + (size_t)code * DDIM + (lane & 3) * 64;
                float a0 = 0.f, a1 = 0.f, a2 = 0.f, a3 = 0.f;
                #pragma unroll
                for (int d = 0; d < 64; d += 16) {
                    float4 za = *(const float4*)(zh + d);
                    float4 zb = *(const float4*)(zh + d + 4);
                    float4 zc = *(const float4*)(zh + d + 8);
                    float4 zd = *(const float4*)(zh + d + 12);
                    float4 wa = *(const float4*)(wp + d);
                    float4 wb = *(const float4*)(wp + d + 4);
                    float4 wc = *(const float4*)(wp + d + 8);
                    float4 wd = *(const float4*)(wp + d + 12);
                    a0 = fmaf(za.x, wa.x, fmaf(za.y, wa.y, fmaf(za.z, wa.z, fmaf(za.w, wa.w, a0))));
                    a1 = fmaf(zb.x, wb.x, fmaf(zb.y, wb.y, fmaf(zb.z, wb.z, fmaf(zb.w, wb.w, a1))));
                    a2 = fmaf(zc.x, wc.x, fmaf(zc.y, wc.y, fmaf(zc.z, wc.z, fmaf(zc.w, wc.w, a2))));
                    a3 = fmaf(zd.x, wd.x, fmaf(zd.y, wd.y, fmaf(zd.z, wd.z, fmaf(zd.w, wd.w, a3))));
                }
                float accv = (a0 + a1) + (a2 + a3);
                accv += __shfl_xor_sync(0xffffffffu, accv, 1);
                accv += __shfl_xor_sync(0xffffffffu, accv, 2);
                if ((lane & 3) == 0)
                    best = umax64(best, fkey(accv - __ldg(&g_wnorm[code]), code));
            }
        }
    }
    #pragma unroll
    for (int off = 16; off > 0; off >>= 1)
        best = umax64(best, __shfl_xor_sync(0xffffffffu, best, off));
    const int idx = KCODES - 1 - (int)(best & 0xffffffffu);

    // ---- fused scatter ----
    const float4* wg = (const float4*)(W + (size_t)idx * DDIM);
    float4 w0 = wg[lane], w1 = wg[lane + 32];

    float4* oq = (float4*)(out_zq + (size_t)row * DDIM);
    float4 q0, q1;   // straight-through: ze + (zq - ze)
    q0.x = z0.x + (w0.x - z0.x); q0.y = z0.y + (w0.y - z0.y);
    q0.z = z0.z + (w0.z - z0.z); q0.w = z0.w + (w0.w - z0.w);
    q1.x = z1.x + (w1.x - z1.x); q1.y = z1.y + (w1.y - z1.y);
    q1.z = z1.z + (w1.z - z1.z); q1.w = z1.w + (w1.w - z1.w);
    oq[lane] = q0; oq[lane + 32] = q1;

    float cs = 0.f;
    {
        float d;
        d = w0.x - z0.x; cs = fmaf(d, d, cs);
        d = w0.y - z0.y; cs = fmaf(d, d, cs);
        d = w0.z - z0.z; cs = fmaf(d, d, cs);
        d = w0.w - z0.w; cs = fmaf(d, d, cs);
        d = w1.x - z1.x; cs = fmaf(d, d, cs);
        d = w1.y - z1.y; cs = fmaf(d, d, cs);
        d = w1.z - z1.z; cs = fmaf(d, d, cs);
        d = w1.w - z1.w; cs = fmaf(d, d, cs);
    }
    #pragma unroll
    for (int off = 16; off > 0; off >>= 1)
        cs += __shfl_xor_sync(0xffffffffu, cs, off);

    const float s = 1.0f - GAMMA_F;
    float* mp = out_mt + (size_t)idx * DDIM + lane * 4;
    atomicAdd(mp + 0, s * z0.x); atomicAdd(mp + 1, s * z0.y);
    atomicAdd(mp + 2, s * z0.z); atomicAdd(mp + 3, s * z0.w);
    float* mp1 = mp + 128;
    atomicAdd(mp1 + 0, s * z1.x); atomicAdd(mp1 + 1, s * z1.y);
    atomicAdd(mp1 + 2, s * z1.z); atomicAdd(mp1 + 3, s * z1.w);

    if (lane == 0) {
        out_idx[row] = (float)idx;
        atomicAdd(&g_cnt[idx], 1.0f);
        atomicAdd(&g_commit, cs);
    }
}

// ---------------- Nt_new + n ----------------
__global__ void k_fin_nt(const float* __restrict__ Nt, float* __restrict__ out_Nt) {
    int k = blockIdx.x * 256 + threadIdx.x;
    float v = GAMMA_F * Nt[k] + (1.0f - GAMMA_F) * g_cnt[k];
    out_Nt[k] = v;
    __shared__ float red[8];
    float s = v;
    #pragma unroll
    for (int off = 16; off > 0; off >>= 1)
        s += __shfl_down_sync(0xffffffffu, s, off);
    if ((threadIdx.x & 31) == 0) red[threadIdx.x >> 5] = s;
    __syncthreads();
    if (threadIdx.x < 8) {
        float t = red[threadIdx.x];
        #pragma unroll
        for (int off = 4; off > 0; off >>= 1)
            t += __shfl_down_sync(0xffu, t, off);
        if (threadIdx.x == 0) atomicAdd(&g_nsum, t);
    }
}

// ---------------- embedW_new + commit ----------------
__global__ void k_fin_w(const float* __restrict__ out_Nt,
                        const float* __restrict__ out_mt,
                        float* __restrict__ out_W,
                        float* __restrict__ out_commit) {
    int i = blockIdx.x * 256 + threadIdx.x;
    int k = i >> 8;
    float n  = g_nsum;
    float Nn = (out_Nt[k] + EPS_F) * n / (n + (float)KCODES * EPS_F);
    out_W[i] = out_mt[i] / Nn;
    if (i == 0) *out_commit = g_commit / (float)((size_t)NROWS * DDIM);
}

// ---------------- launch ----------------
extern "C" void kernel_launch(void* const* d_in, const int* in_sizes, int n_in,
                              void* d_out, int out_size) {
    const float* ze = (const float*)d_in[0];
    const float* W  = (const float*)d_in[1];
    const float* mt = (const float*)d_in[2];
    const float* Nt = (const float*)d_in[3];
    float* out = (float*)d_out;

    const size_t off_zq     = 0;
    const size_t off_commit = (size_t)NROWS * DDIM;
    const size_t off_idx    = off_commit + 1;
    const size_t off_W      = off_idx + NROWS;
    const size_t off_mt     = off_W + (size_t)KCODES * DDIM;
    const size_t off_Nt     = off_mt + (size_t)KCODES * DDIM;

    static int done = 0;
    if (!done) {
        cudaFuncSetAttribute(k_gemm1, cudaFuncAttributeMaxDynamicSharedMemorySize,
                             GEMM_SMEM);
        done = 1;
    }

    k_prep<<<(NROWS * DDIM) / 256, 256>>>(ze, W);
    k_init<<<(KCODES * DDIM) / 256, 256>>>(W, mt, out + off_mt);

    dim3 grid(NROWS / 128, KCODES / 128);
    k_gemm1<<<grid, 256, GEMM_SMEM>>>();

    k_phase2<<<NROWS / 8, 256>>>(ze, W, out + off_zq, out + off_idx, out + off_mt);
    k_fin_nt<<<KCODES / 256, 256>>>(Nt, out + off_Nt);
    k_fin_w<<<(KCODES * DDIM) / 256, 256>>>(out + off_Nt, out + off_mt,
                                            out + off_W, out + off_commit);
}

// round 16
// speedup vs baseline: 1.3131x; 1.1415x over previous
#include <cuda_runtime.h>
#include <cuda_fp16.h>
#include <cstdint>
#include <cstddef>

#define KCODES 8192
#define DDIM   256
#define NROWS  32768
#define GAMMA_F 0.99f
#define EPS_F   1e-5f

#define NKC  8              // K-chunks of 32 halves (K=256)
#define NS   4              // cp.async pipeline stages
#define LDH  40             // padded halves per smem row (80B)
#define GEMM_SMEM (2 * NS * 128 * LDH * 2)   // 81920 B
#define MARGIN 0.19f
#define NGRP (KCODES / 8)   // 1024 8-code groups
#define NTIL (KCODES / 64)  // 128 64-code tiles

// ---------------- device scratch ----------------
__device__ __half g_Az[(size_t)NROWS * DDIM];
__device__ __half g_Bw[(size_t)KCODES * DDIM];
__device__ __half g_S[(size_t)NROWS * NGRP];     // per (row,8-code group) max approx score (fp16)
__device__ float  g_T[(size_t)NROWS * NTIL];     // per (row,64-code tile) max approx score
__device__ float g_wnorm[KCODES];
__device__ float g_cnt[KCODES];
__device__ float g_commit;
__device__ float g_nsum;

// ---------------- helpers ----------------
__device__ __forceinline__ uint32_t smem_u32(const void* p) {
    uint32_t a;
    asm("{ .reg .u64 t; cvta.to.shared.u64 t, %1; cvt.u32.u64 %0, t; }" : "=r"(a) : "l"(p));
    return a;
}
__device__ __forceinline__ void cp16(uint32_t s, const void* g) {
    asm volatile("cp.async.cg.shared.global [%0], [%1], 16;" :: "r"(s), "l"(g));
}
#define CP_COMMIT() asm volatile("cp.async.commit_group;" ::: "memory")
#define CP_WAIT(n)  asm volatile("cp.async.wait_group %0;" :: "n"(n) : "memory")

__device__ __forceinline__ void ldsm4(uint32_t* r, uint32_t addr) {
    asm volatile("ldmatrix.sync.aligned.m8n8.x4.shared.b16 {%0,%1,%2,%3}, [%4];"
                 : "=r"(r[0]), "=r"(r[1]), "=r"(r[2]), "=r"(r[3]) : "r"(addr));
}
__device__ __forceinline__ void mma16816(float* c, const uint32_t* a,
                                         uint32_t b0, uint32_t b1) {
    asm volatile(
        "mma.sync.aligned.m16n8k16.row.col.f32.f16.f16.f32 "
        "{%0,%1,%2,%3}, {%4,%5,%6,%7}, {%8,%9}, {%0,%1,%2,%3};"
        : "+f"(c[0]), "+f"(c[1]), "+f"(c[2]), "+f"(c[3])
        : "r"(a[0]), "r"(a[1]), "r"(a[2]), "r"(a[3]), "r"(b0), "r"(b1));
}
__device__ __forceinline__ unsigned long long fkey(float s, int code) {
    unsigned u = __float_as_uint(s);
    u = (u & 0x80000000u) ? ~u : (u | 0x80000000u);
    return ((unsigned long long)u << 32) | (unsigned)(KCODES - 1 - code);
}
__device__ __forceinline__ unsigned long long umax64(unsigned long long a, unsigned long long b) {
    return a > b ? a : b;
}

// ---------------- prep: casts + mt seed + wnorm + scalars (merged) ----------------
__global__ void k_prep(const float* __restrict__ ze, const float* __restrict__ W,
                       const float* __restrict__ mt, float* __restrict__ out_mt) {
    int i = blockIdx.x * 256 + threadIdx.x;       // covers NROWS*DDIM
    g_Az[i] = __float2half_rn(ze[i]);
    if (i < KCODES * DDIM) {
        g_Bw[i] = __float2half_rn(W[i]);
        out_mt[i] = GAMMA_F * mt[i];
    }
    if (i < KCODES) {
        const float4* w = (const float4*)(W + (size_t)i * DDIM);
        float s = 0.f;
        #pragma unroll 8
        for (int q = 0; q < DDIM / 4; ++q) {
            float4 v = w[q];
            s += v.x * v.x + v.y * v.y + v.z * v.z + v.w * v.w;
        }
        g_wnorm[i] = 0.5f * s;
        g_cnt[i]   = 0.f;
    }
    if (i == 0) { g_commit = 0.f; g_nsum = 0.f; }
}

// ---------------- phase 1: fp16 HMMA (f32 accum) approx GEMM ----------------
__global__ void __launch_bounds__(256, 2) k_gemm1() {
    extern __shared__ __half dsm[];
    __half* sAb = dsm;                       // [NS][128*LDH]
    __half* sBb = dsm + NS * 128 * LDH;

    const int tid  = threadIdx.x;
    const int wid  = tid >> 5;
    const int lane = tid & 31;
    const int rowBase = blockIdx.x * 128;
    const int nBase   = blockIdx.y * 128;

    const int lr = tid >> 2;
    const int lc = tid & 3;
    uint32_t aS[NS], bS[NS];
    #pragma unroll
    for (int s = 0; s < NS; ++s) {
        aS[s] = smem_u32(sAb + s * 128 * LDH);
        bS[s] = smem_u32(sBb + s * 128 * LDH);
    }

    float acc[2][8][4];
    #pragma unroll
    for (int i = 0; i < 2; ++i)
        #pragma unroll
        for (int j = 0; j < 8; ++j)
            #pragma unroll
            for (int q = 0; q < 4; ++q) acc[i][j][q] = 0.f;

    // prologue: stages 0..NS-2
    #pragma unroll
    for (int s = 0; s < NS - 1; ++s) {
        const int ko = s * 32;
        #pragma unroll
        for (int p = 0; p < 2; ++p) {
            int r = lr + 64 * p;
            cp16(aS[s] + r * (LDH * 2) + lc * 16,
                 g_Az + (size_t)(rowBase + r) * DDIM + ko + lc * 8);
            cp16(bS[s] + r * (LDH * 2) + lc * 16,
                 g_Bw + (size_t)(nBase + r) * DDIM + ko + lc * 8);
        }
        CP_COMMIT();
    }

    const int mOff = (wid >> 1) * 32;
    const int nOff = (wid & 1) * 64;
    const int lmRow = lane & 15;
    const int lmCol = (lane >> 4) * 16;

    for (int kc = 0; kc < NKC; ++kc) {
        CP_WAIT(NS - 2);
        __syncthreads();
        {
            const int nc = kc + NS - 1;
            if (nc < NKC) {
                const int st = nc & (NS - 1);
                const int ko = nc * 32;
                #pragma unroll
                for (int p = 0; p < 2; ++p) {
                    int r = lr + 64 * p;
                    cp16(aS[st] + r * (LDH * 2) + lc * 16,
                         g_Az + (size_t)(rowBase + r) * DDIM + ko + lc * 8);
                    cp16(bS[st] + r * (LDH * 2) + lc * 16,
                         g_Bw + (size_t)(nBase + r) * DDIM + ko + lc * 8);
                }
            }
            CP_COMMIT();
        }

        const int buf = kc & (NS - 1);
        #pragma unroll
        for (int k16 = 0; k16 < 2; ++k16) {
            const int kb = k16 * 32 + lmCol;
            uint32_t af[2][4];
            #pragma unroll
            for (int i = 0; i < 2; ++i)
                ldsm4(af[i], aS[buf] + (mOff + i * 16 + lmRow) * (LDH * 2) + kb);
            uint32_t bf[4][4];
            #pragma unroll
            for (int g = 0; g < 4; ++g)
                ldsm4(bf[g], bS[buf] + (nOff + g * 16 + lmRow) * (LDH * 2) + kb);
            #pragma unroll
            for (int i = 0; i < 2; ++i)
                #pragma unroll
                for (int j = 0; j < 8; ++j) {
                    const int g = j >> 1, h = j & 1;
                    mma16816(acc[i][j], af[i], bf[g][h], bf[g][h + 2]);
                }
        }
    }

    // epilogue: per-8-code-group (half2 packed) and per-tile max scores (unique writer)
    const int gBase = (nBase + nOff) >> 3;   // 8-code groups, multiple of 8
    const int tIdx  = (nBase + nOff) >> 6;
    #pragma unroll
    for (int i = 0; i < 2; ++i) {
        const int r0 = rowBase + mOff + i * 16 + (lane >> 2);   // rows r0, r0+8
        float ta = -3.4e38f, tb = -3.4e38f;
        #pragma unroll
        for (int j2 = 0; j2 < 4; ++j2) {
            float sa[2], sb[2];
            #pragma unroll
            for (int jj = 0; jj < 2; ++jj) {
                const int j = 2 * j2 + jj;
                const int col = nBase + nOff + j * 8 + (lane & 3) * 2;
                const float wn0 = __ldg(&g_wnorm[col]);
                const float wn1 = __ldg(&g_wnorm[col + 1]);
                float va = fmaxf(acc[i][j][0] - wn0, acc[i][j][1] - wn1);
                float vb = fmaxf(acc[i][j][2] - wn0, acc[i][j][3] - wn1);
                va = fmaxf(va, __shfl_xor_sync(0xffffffffu, va, 1));
                va = fmaxf(va, __shfl_xor_sync(0xffffffffu, va, 2));
                vb = fmaxf(vb, __shfl_xor_sync(0xffffffffu, vb, 1));
                vb = fmaxf(vb, __shfl_xor_sync(0xffffffffu, vb, 2));
                sa[jj] = va; sb[jj] = vb;
                ta = fmaxf(ta, va); tb = fmaxf(tb, vb);
            }
            if ((lane & 3) == 0) {
                __half2 ha = __halves2half2(__float2half_rn(sa[0]), __float2half_rn(sa[1]));
                __half2 hb = __halves2half2(__float2half_rn(sb[0]), __float2half_rn(sb[1]));
                *(__half2*)(g_S + (size_t)r0 * NGRP + gBase + 2 * j2)       = ha;
                *(__half2*)(g_S + (size_t)(r0 + 8) * NGRP + gBase + 2 * j2) = hb;
            }
        }
        if ((lane & 3) == 0) {
            g_T[(size_t)r0 * NTIL + tIdx]       = ta;
            g_T[(size_t)(r0 + 8) * NTIL + tIdx] = tb;
        }
    }
}

// ---------------- phase 2: hierarchical prune + exact fp32 rescore + fused scatter ----------------
__global__ void __launch_bounds__(256, 4) k_phase2(const float* __restrict__ ze,
                                                   const float* __restrict__ W,
                                                   float* __restrict__ out_zq,
                                                   float* __restrict__ out_idx,
                                                   float* __restrict__ out_mt) {
    __shared__ float zs[8][DDIM];
    const int wid  = threadIdx.x >> 5;
    const int lane = threadIdx.x & 31;
    const int row  = blockIdx.x * 8 + wid;

    float4 z0, z1;
    {
        const float4* zg = (const float4*)(ze + (size_t)row * DDIM);
        z0 = zg[lane]; z1 = zg[lane + 32];
        ((float4*)zs[wid])[lane]      = z0;
        ((float4*)zs[wid])[lane + 32] = z1;
    }
    __syncwarp();

    // scan per-tile maxima (128 floats)
    const float* Trow = g_T + (size_t)row * NTIL;
    float tv[4];
    float m = -3.4e38f;
    #pragma unroll
    for (int i = 0; i < 4; ++i) {
        tv[i] = Trow[i * 32 + lane];
        m = fmaxf(m, tv[i]);
    }
    #pragma unroll
    for (int off = 16; off > 0; off >>= 1)
        m = fmaxf(m, __shfl_xor_sync(0xffffffffu, m, off));
    const float thr = m - MARGIN;

    const __half* Srow = g_S + (size_t)row * NGRP;
    unsigned long long best = 0ull;
    const float* zh = zs[wid] + (lane & 3) * 64;
    #pragma unroll
    for (int i = 0; i < 4; ++i) {
        unsigned tmask = __ballot_sync(0xffffffffu, tv[i] >= thr);
        while (tmask) {
            const int tb = __ffs(tmask) - 1;
            tmask &= tmask - 1;
            const int tile = i * 32 + tb;
            // this tile's 8 group scores (lanes 0-7)
            float gsv = (lane < 8) ? __half2float(Srow[tile * 8 + lane]) : -3.4e38f;
            unsigned gmask = __ballot_sync(0xffffffffu, gsv >= thr) & 0xFFu;
            while (gmask) {
                const int gb = __ffs(gmask) - 1;
                gmask &= gmask - 1;
                const int g = tile * 8 + gb;
                const int code = g * 8 + (lane >> 2);    // 4 lanes per code
                const float* wp = W + (size_t)code * DDIM + (lane & 3) * 64;
                float a0 = 0.f, a1 = 0.f, a2 = 0.f, a3 = 0.f;
                #pragma unroll
                for (int d = 0; d < 64; d += 16) {
                    float4 za = *(const float4*)(zh + d);
                    float4 zb = *(const float4*)(zh + d + 4);
                    float4 zc = *(const float4*)(zh + d + 8);
                    float4 zd = *(const float4*)(zh + d + 12);
                    float4 wa = *(const float4*)(wp + d);
                    float4 wb = *(const float4*)(wp + d + 4);
                    float4 wc = *(const float4*)(wp + d + 8);
                    float4 wd = *(const float4*)(wp + d + 12);
                    a0 = fmaf(za.x, wa.x, fmaf(za.y, wa.y, fmaf(za.z, wa.z, fmaf(za.w, wa.w, a0))));
                    a1 = fmaf(zb.x, wb.x, fmaf(zb.y, wb.y, fmaf(zb.z, wb.z, fmaf(zb.w, wb.w, a1))));
                    a2 = fmaf(zc.x, wc.x, fmaf(zc.y, wc.y, fmaf(zc.z, wc.z, fmaf(zc.w, wc.w, a2))));
                    a3 = fmaf(zd.x, wd.x, fmaf(zd.y, wd.y, fmaf(zd.z, wd.z, fmaf(zd.w, wd.w, a3))));
                }
                float accv = (a0 + a1) + (a2 + a3);
                accv += __shfl_xor_sync(0xffffffffu, accv, 1);
                accv += __shfl_xor_sync(0xffffffffu, accv, 2);
                if ((lane & 3) == 0)
                    best = umax64(best, fkey(accv - __ldg(&g_wnorm[code]), code));
            }
        }
    }
    #pragma unroll
    for (int off = 16; off > 0; off >>= 1)
        best = umax64(best, __shfl_xor_sync(0xffffffffu, best, off));
    const int idx = KCODES - 1 - (int)(best & 0xffffffffu);

    // ---- fused scatter ----
    const float4* wg = (const float4*)(W + (size_t)idx * DDIM);
    float4 w0 = wg[lane], w1 = wg[lane + 32];

    float4* oq = (float4*)(out_zq + (size_t)row * DDIM);
    float4 q0, q1;   // straight-through: ze + (zq - ze)
    q0.x = z0.x + (w0.x - z0.x); q0.y = z0.y + (w0.y - z0.y);
    q0.z = z0.z + (w0.z - z0.z); q0.w = z0.w + (w0.w - z0.w);
    q1.x = z1.x + (w1.x - z1.x); q1.y = z1.y + (w1.y - z1.y);
    q1.z = z1.z + (w1.z - z1.z); q1.w = z1.w + (w1.w - z1.w);
    oq[lane] = q0; oq[lane + 32] = q1;

    float cs = 0.f;
    {
        float d;
        d = w0.x - z0.x; cs = fmaf(d, d, cs);
        d = w0.y - z0.y; cs = fmaf(d, d, cs);
        d = w0.z - z0.z; cs = fmaf(d, d, cs);
        d = w0.w - z0.w; cs = fmaf(d, d, cs);
        d = w1.x - z1.x; cs = fmaf(d, d, cs);
        d = w1.y - z1.y; cs = fmaf(d, d, cs);
        d = w1.z - z1.z; cs = fmaf(d, d, cs);
        d = w1.w - z1.w; cs = fmaf(d, d, cs);
    }
    #pragma unroll
    for (int off = 16; off > 0; off >>= 1)
        cs += __shfl_xor_sync(0xffffffffu, cs, off);

    const float s = 1.0f - GAMMA_F;
    float* mp = out_mt + (size_t)idx * DDIM + lane * 4;
    atomicAdd(mp + 0, s * z0.x); atomicAdd(mp + 1, s * z0.y);
    atomicAdd(mp + 2, s * z0.z); atomicAdd(mp + 3, s * z0.w);
    float* mp1 = mp + 128;
    atomicAdd(mp1 + 0, s * z1.x); atomicAdd(mp1 + 1, s * z1.y);
    atomicAdd(mp1 + 2, s * z1.z); atomicAdd(mp1 + 3, s * z1.w);

    if (lane == 0) {
        out_idx[row] = (float)idx;
        atomicAdd(&g_cnt[idx], 1.0f);
        atomicAdd(&g_commit, cs);
    }
}

// ---------------- Nt_new + n ----------------
__global__ void k_fin_nt(const float* __restrict__ Nt, float* __restrict__ out_Nt) {
    int k = blockIdx.x * 256 + threadIdx.x;
    float v = GAMMA_F * Nt[k] + (1.0f - GAMMA_F) * g_cnt[k];
    out_Nt[k] = v;
    __shared__ float red[8];
    float s = v;
    #pragma unroll
    for (int off = 16; off > 0; off >>= 1)
        s += __shfl_down_sync(0xffffffffu, s, off);
    if ((threadIdx.x & 31) == 0) red[threadIdx.x >> 5] = s;
    __syncthreads();
    if (threadIdx.x < 8) {
        float t = red[threadIdx.x];
        #pragma unroll
        for (int off = 4; off > 0; off >>= 1)
            t += __shfl_down_sync(0xffu, t, off);
        if (threadIdx.x == 0) atomicAdd(&g_nsum, t);
    }
}

// ---------------- embedW_new + commit ----------------
__global__ void k_fin_w(const float* __restrict__ out_Nt,
                        const float* __restrict__ out_mt,
                        float* __restrict__ out_W,
                        float* __restrict__ out_commit) {
    int i = blockIdx.x * 256 + threadIdx.x;
    int k = i >> 8;
    float n  = g_nsum;
    float Nn = (out_Nt[k] + EPS_F) * n / (n + (float)KCODES * EPS_F);
    out_W[i] = out_mt[i] / Nn;
    if (i == 0) *out_commit = g_commit / (float)((size_t)NROWS * DDIM);
}

// ---------------- launch ----------------
extern "C" void kernel_launch(void* const* d_in, const int* in_sizes, int n_in,
                              void* d_out, int out_size) {
    const float* ze = (const float*)d_in[0];
    const float* W  = (const float*)d_in[1];
    const float* mt = (const float*)d_in[2];
    const float* Nt = (const float*)d_in[3];
    float* out = (float*)d_out;

    const size_t off_zq     = 0;
    const size_t off_commit = (size_t)NROWS * DDIM;
    const size_t off_idx    = off_commit + 1;
    const size_t off_W      = off_idx + NROWS;
    const size_t off_mt     = off_W + (size_t)KCODES * DDIM;
    const size_t off_Nt     = off_mt + (size_t)KCODES * DDIM;

    static int done = 0;
    if (!done) {
        cudaFuncSetAttribute(k_gemm1, cudaFuncAttributeMaxDynamicSharedMemorySize,
                             GEMM_SMEM);
        done = 1;
    }

    k_prep<<<(NROWS * DDIM) / 256, 256>>>(ze, W, mt, out + off_mt);

    dim3 grid(NROWS / 128, KCODES / 128);
    k_gemm1<<<grid, 256, GEMM_SMEM>>>();

    k_phase2<<<NROWS / 8, 256>>>(ze, W, out + off_zq, out + off_idx, out + off_mt);
    k_fin_nt<<<KCODES / 256, 256>>>(Nt, out + off_Nt);
    k_fin_w<<<(KCODES * DDIM) / 256, 256>>>(out + off_Nt, out + off_mt,
                                            out + off_W, out + off_commit);
}